// round 17
// baseline (speedup 1.0000x reference)
#include <cuda_runtime.h>
#include <cuda_fp16.h>
#include <cstdint>
#include <math.h>

// Problem constants
#define BB   2
#define SS   2048
#define DD   1024
#define HH   16
#define DKH  64          // head dim
#define MTOT (BB*SS)     // 4096 rows

typedef __half h16;

// -------- scratch (static device globals; allocation-free) --------
__device__ float2 g_trig[SS * 32];                  // cos/sin table [s][p]

__device__ h16 g_x_h  [(size_t)MTOT * DD];          // single fp16
__device__ h16 g_wq_h [(size_t)3 * DD * DD];        // single fp16
__device__ h16 g_ao_h [(size_t)MTOT * DD];          // single fp16
__device__ h16 g_wo_h [(size_t)DD * DD];            // single fp16

// attention operands (all single fp16)
__device__ h16 g_qh[(size_t)BB * HH * SS * DKH];    // [b,h,s,d]
__device__ h16 g_kh[(size_t)BB * HH * SS * DKH];
__device__ h16 g_vth[(size_t)BB * HH * DKH * SS];   // [b,h,d,s]

// ============================================================================
// helpers
// ============================================================================
__device__ __forceinline__ void mma16816(float* d,
                                         const uint32_t* a, const uint32_t* b) {
    asm volatile(
        "mma.sync.aligned.m16n8k16.row.col.f32.f16.f16.f32 "
        "{%0,%1,%2,%3}, {%4,%5,%6,%7}, {%8,%9}, {%0,%1,%2,%3};"
        : "+f"(d[0]), "+f"(d[1]), "+f"(d[2]), "+f"(d[3])
        : "r"(a[0]), "r"(a[1]), "r"(a[2]), "r"(a[3]), "r"(b[0]), "r"(b[1]));
}

// pack two f32 -> f16x2 (lo = a, hi = b)
__device__ __forceinline__ uint32_t pack_h2(float a, float b) {
    uint32_t r;
    asm("cvt.rn.f16x2.f32 %0, %1, %2;" : "=r"(r) : "f"(b), "f"(a));
    return r;
}

__device__ __forceinline__ uint32_t sptr(const void* p) {
    uint32_t a;
    asm("{ .reg .u64 t; cvta.to.shared.u64 t, %1; cvt.u32.u64 %0, t; }" : "=r"(a) : "l"(p));
    return a;
}
#define CP16(dst, src) \
    asm volatile("cp.async.cg.shared.global [%0], [%1], 16;" :: "r"(sptr(dst)), "l"(src))
#define CP_COMMIT()  asm volatile("cp.async.commit_group;" ::: "memory")
#define CP_WAIT1()   asm volatile("cp.async.wait_group 1;" ::: "memory")
#define CP_WAIT0()   asm volatile("cp.async.wait_group 0;" ::: "memory")

// ============================================================================
// fp32 -> fp16 convert
// ============================================================================
__global__ void cvt_kernel(const float* __restrict__ src, h16* __restrict__ dst, int n) {
    int i = blockIdx.x * blockDim.x + threadIdx.x;
    if (i >= n) return;
    dst[i] = __float2half_rn(src[i]);
}

// ============================================================================
// trig table
// ============================================================================
__global__ void trig_kernel(float2* __restrict__ T) {
    int idx = blockIdx.x * blockDim.x + threadIdx.x;
    if (idx >= SS * 32) return;
    int p = idx & 31, s = idx >> 5;
    float inv = 1.0f / powf(50.0f, (2.0f * (float)p) / 64.0f);
    float ang = (float)s * inv;
    double sd, cd;
    sincos((double)ang, &sd, &cd);
    T[idx] = make_float2((float)cd, (float)sd);
}

// ============================================================================
// Fused QKV GEMM (1-term fp16): warp tile 64x64, 128 thr = 4 warps (2x2).
// BM=BN=128, BK=32, cp.async 2-stage. Epilogue RoPE + layouts.
// ============================================================================
#define GST 40
#define G_ARR (128 * GST)
#define G_STAGE2 (2 * G_ARR)
#define G_SMEM2 (2 * G_STAGE2 * 2)

__global__ __launch_bounds__(128)
void wgemm_qkv_rope(const h16* __restrict__ Ah, const h16* __restrict__ Bh,
                    const float2* __restrict__ T,
                    h16* __restrict__ Qh, h16* __restrict__ Kh,
                    h16* __restrict__ Vth)
{
    extern __shared__ h16 dsm[];
    const int K = DD;

    const int tid  = threadIdx.x;
    const int wid  = tid >> 5;
    const int lane = tid & 31;
    const int lr   = lane >> 2;
    const int lc   = (lane & 3) * 2;

    const int mbase = blockIdx.y * 128;
    const int nbase = blockIdx.x * 128;
    const int wm = (wid >> 1) * 64;
    const int wn = (wid & 1) * 64;

    float acc[4][8][4];
    #pragma unroll
    for (int mi = 0; mi < 4; mi++)
        #pragma unroll
        for (int ni = 0; ni < 8; ni++)
            #pragma unroll
            for (int r = 0; r < 4; r++) acc[mi][ni][r] = 0.f;

    const int lrow = tid >> 2;          // 0..31
    const int lch  = tid & 3;
    auto issue_chunk = [&](int k0, int st) {
        h16* base = dsm + st * G_STAGE2;
        #pragma unroll
        for (int rep = 0; rep < 4; rep++) {
            int row = lrow + rep * 32;
            size_t sa = (size_t)(mbase + row) * K + k0 + lch * 8;
            size_t sb = (size_t)(nbase + row) * K + k0 + lch * 8;
            CP16(base + 0 * G_ARR + row * GST + lch * 8, Ah + sa);
            CP16(base + 1 * G_ARR + row * GST + lch * 8, Bh + sb);
        }
        CP_COMMIT();
    };

    const int NCH = K >> 5;
    issue_chunk(0, 0);

    for (int ch = 0; ch < NCH; ++ch) {
        const int cur = ch & 1;
        if (ch + 1 < NCH) { issue_chunk((ch + 1) << 5, cur ^ 1); CP_WAIT1(); }
        else              { CP_WAIT0(); }
        __syncthreads();

        const h16* sA = dsm + cur * G_STAGE2 + 0 * G_ARR;
        const h16* sB = dsm + cur * G_STAGE2 + 1 * G_ARR;

        #pragma unroll
        for (int ks = 0; ks < 32; ks += 16) {
            uint32_t af[4][4];
            #pragma unroll
            for (int mi = 0; mi < 4; mi++) {
                int r0 = wm + mi * 16 + lr;
                af[mi][0] = *(const uint32_t*)(sA + (r0    ) * GST + ks + lc);
                af[mi][1] = *(const uint32_t*)(sA + (r0 + 8) * GST + ks + lc);
                af[mi][2] = *(const uint32_t*)(sA + (r0    ) * GST + ks + 8 + lc);
                af[mi][3] = *(const uint32_t*)(sA + (r0 + 8) * GST + ks + 8 + lc);
            }
            uint32_t bf[8][2];
            #pragma unroll
            for (int ni = 0; ni < 8; ni++) {
                int rn = wn + ni * 8 + lr;
                bf[ni][0] = *(const uint32_t*)(sB + rn * GST + ks + lc);
                bf[ni][1] = *(const uint32_t*)(sB + rn * GST + ks + 8 + lc);
            }
            #pragma unroll
            for (int mi = 0; mi < 4; mi++)
                #pragma unroll
                for (int ni = 0; ni < 8; ni++)
                    mma16816(acc[mi][ni], af[mi], bf[ni]);
        }
        __syncthreads();
    }

    // ---- fused epilogue: RoPE + convert + layout ----
    const int sec = nbase >> 10;            // 0=Q, 1=K, 2=V
    #pragma unroll
    for (int mi = 0; mi < 4; mi++) {
        const int row0 = mbase + wm + mi * 16 + lr;
        #pragma unroll
        for (int ni = 0; ni < 8; ni++) {
            const int gcol = nbase + wn + ni * 8 + lc;
            const int c  = gcol & 1023;
            const int h  = c >> 6;
            const int d  = c & 63;
            #pragma unroll
            for (int half = 0; half < 2; half++) {
                const int grow = row0 + half * 8;
                const int b = grow >> 11;
                const int s = grow & (SS - 1);
                const float v0 = acc[mi][ni][half * 2 + 0];
                const float v1 = acc[mi][ni][half * 2 + 1];
                if (sec < 2) {
                    const float2 cs = T[s * 32 + (d >> 1)];
                    const float r0 = v0 * cs.x - v1 * cs.y;
                    const float r1 = v1 * cs.x + v0 * cs.y;
                    const size_t o = ((size_t)(b * HH + h) * SS + s) * DKH + d;
                    if (sec == 0) {
                        Qh[o]     = __float2half_rn(r0);
                        Qh[o + 1] = __float2half_rn(r1);
                    } else {
                        Kh[o]     = __float2half_rn(r0);
                        Kh[o + 1] = __float2half_rn(r1);
                    }
                } else {
                    const size_t o = ((size_t)(b * HH + h) * DKH + d) * SS + s;
                    Vth[o]      = __float2half_rn(v0);
                    Vth[o + SS] = __float2half_rn(v1);
                }
            }
        }
    }
}

// ============================================================================
// Tensor-core flash attention, fp16, fixed-offset softmax.
// 128 thr = 4 warps, each warp 32 q rows (2 row groups of 16). BM=128.
// Each K/V fragment LDS feeds 2 MMAs (both row groups): 16 FLOP/B.
// ============================================================================
#define AST 72                       // smem row stride in halves (144B)
#define A_ARR (64 * AST)
#define A_STAGE (2 * A_ARR)          // K + V
#define A_SMEM_BYTES (2 * A_STAGE * 2)

__global__ __launch_bounds__(128) void attn_mma(
    const h16* __restrict__ Qh, const h16* __restrict__ Kh,
    const h16* __restrict__ Vth, h16* __restrict__ Oh)
{
    extern __shared__ h16 dsm[];

    const int tid  = threadIdx.x;
    const int wid  = tid >> 5;
    const int lane = tid & 31;
    const int g    = lane >> 2;
    const int t4   = lane & 3;

    const int bh = blockIdx.y;
    const int b  = bh >> 4;
    const int h  = bh & 15;
    const int q0 = blockIdx.x * 128 + wid * 32;   // warp's first q row (32 rows)

    // Q fragments for 2 row groups
    uint32_t qf[2][4][4];
    #pragma unroll
    for (int rg2 = 0; rg2 < 2; rg2++) {
        const h16* Qb = Qh + ((size_t)bh * SS + q0 + rg2 * 16) * DKH;
        #pragma unroll
        for (int ks = 0; ks < 4; ks++) {
            const int c0 = ks * 16 + 2 * t4;
            qf[rg2][ks][0] = *(const uint32_t*)(Qb + (size_t)g * DKH + c0);
            qf[rg2][ks][1] = *(const uint32_t*)(Qb + (size_t)(g + 8) * DKH + c0);
            qf[rg2][ks][2] = *(const uint32_t*)(Qb + (size_t)g * DKH + c0 + 8);
            qf[rg2][ks][3] = *(const uint32_t*)(Qb + (size_t)(g + 8) * DKH + c0 + 8);
        }
    }

    float l[2][2] = {{0.f, 0.f}, {0.f, 0.f}};
    float acc[2][8][4];
    #pragma unroll
    for (int rg2 = 0; rg2 < 2; rg2++)
        #pragma unroll
        for (int n = 0; n < 8; n++)
            #pragma unroll
            for (int r = 0; r < 4; r++) acc[rg2][n][r] = 0.f;

    const float SC2 = 0.125f * 1.44269504088896340736f;
    const float FM  = 4.0f;

    const h16* Kb = Kh + (size_t)bh * SS * DKH;
    const h16* Vb = Vth + (size_t)bh * DKH * SS;

    const int lrow = tid >> 3;          // 0..15
    const int lch  = tid & 7;
    auto issue_tile = [&](int t, int st) {
        h16* base = dsm + st * A_STAGE;
        #pragma unroll
        for (int rep = 0; rep < 4; rep++) {
            int row = lrow + rep * 16;
            size_t sk = (size_t)(t * 64 + row) * DKH + lch * 8;
            size_t sv = (size_t)row * SS + t * 64 + lch * 8;
            CP16(base + 0 * A_ARR + row * AST + lch * 8, Kb + sk);
            CP16(base + 1 * A_ARR + row * AST + lch * 8, Vb + sv);
        }
        CP_COMMIT();
    };

    const int NT = SS / 64;
    issue_tile(0, 0);

    for (int t = 0; t < NT; ++t) {
        const int cur = t & 1;
        if (t + 1 < NT) { issue_tile(t + 1, cur ^ 1); CP_WAIT1(); }
        else            { CP_WAIT0(); }
        __syncthreads();

        const h16* sK = dsm + cur * A_STAGE + 0 * A_ARR;
        const h16* sV = dsm + cur * A_STAGE + 1 * A_ARR;

        // ---- S = Q K^T (both row groups share K frags) ----
        float S[2][8][4];
        #pragma unroll
        for (int j = 0; j < 8; j++) {
            S[0][j][0] = S[0][j][1] = S[0][j][2] = S[0][j][3] = 0.f;
            S[1][j][0] = S[1][j][1] = S[1][j][2] = S[1][j][3] = 0.f;
            #pragma unroll
            for (int ks = 0; ks < 4; ks++) {
                const int ko = ks * 16 + 2 * t4;
                uint32_t bf[2];
                bf[0] = *(const uint32_t*)(sK + (8 * j + g) * AST + ko);
                bf[1] = *(const uint32_t*)(sK + (8 * j + g) * AST + ko + 8);
                mma16816(S[0][j], qf[0][ks], bf);
                mma16816(S[1][j], qf[1][ks], bf);
            }
        }

        // ---- fixed-offset softmax + pack P ----
        uint32_t ph[2][4][4];
        #pragma unroll
        for (int rg2 = 0; rg2 < 2; rg2++) {
            const int rgq  = q0 + rg2 * 16 + g;
            const int rgq8 = rgq + 8;
            float rs0 = 0.f, rs1 = 0.f;
            #pragma unroll
            for (int j = 0; j < 8; j++) {
                int k0i = t * 64 + 8 * j + 2 * t4;
                S[rg2][j][0] = (k0i     == rgq ) ? 0.f : exp2f(S[rg2][j][0] * SC2 - FM);
                S[rg2][j][1] = (k0i + 1 == rgq ) ? 0.f : exp2f(S[rg2][j][1] * SC2 - FM);
                S[rg2][j][2] = (k0i     == rgq8) ? 0.f : exp2f(S[rg2][j][2] * SC2 - FM);
                S[rg2][j][3] = (k0i + 1 == rgq8) ? 0.f : exp2f(S[rg2][j][3] * SC2 - FM);
                rs0 += S[rg2][j][0] + S[rg2][j][1];
                rs1 += S[rg2][j][2] + S[rg2][j][3];
            }
            rs0 += __shfl_xor_sync(0xffffffffu, rs0, 1);
            rs0 += __shfl_xor_sync(0xffffffffu, rs0, 2);
            rs1 += __shfl_xor_sync(0xffffffffu, rs1, 1);
            rs1 += __shfl_xor_sync(0xffffffffu, rs1, 2);
            l[rg2][0] += rs0;
            l[rg2][1] += rs1;

            #pragma unroll
            for (int q = 0; q < 4; q++) {
                const int j0 = 2 * q, j1 = 2 * q + 1;
                ph[rg2][q][0] = pack_h2(S[rg2][j0][0], S[rg2][j0][1]);
                ph[rg2][q][1] = pack_h2(S[rg2][j0][2], S[rg2][j0][3]);
                ph[rg2][q][2] = pack_h2(S[rg2][j1][0], S[rg2][j1][1]);
                ph[rg2][q][3] = pack_h2(S[rg2][j1][2], S[rg2][j1][3]);
            }
        }

        // ---- O += P V (both row groups share V frags) ----
        #pragma unroll
        for (int n = 0; n < 8; n++) {
            #pragma unroll
            for (int q = 0; q < 4; q++) {
                const int ko = q * 16 + 2 * t4;
                uint32_t vf[2];
                vf[0] = *(const uint32_t*)(sV + (8 * n + g) * AST + ko);
                vf[1] = *(const uint32_t*)(sV + (8 * n + g) * AST + ko + 8);
                mma16816(acc[0][n], ph[0][q], vf);
                mma16816(acc[1][n], ph[1][q], vf);
            }
        }
        __syncthreads();
    }

    // ---- epilogue ----
    #pragma unroll
    for (int rg2 = 0; rg2 < 2; rg2++) {
        const int rgq  = q0 + rg2 * 16 + g;
        const float inv0 = 1.0f / l[rg2][0], inv1 = 1.0f / l[rg2][1];
        size_t o0 = ((size_t)(b * SS + rgq    )) * DD + h * DKH;
        size_t o1 = ((size_t)(b * SS + rgq + 8)) * DD + h * DKH;
        #pragma unroll
        for (int n = 0; n < 8; n++) {
            const int c = 8 * n + 2 * t4;
            Oh[o0 + c]     = __float2half_rn(acc[rg2][n][0] * inv0);
            Oh[o0 + c + 1] = __float2half_rn(acc[rg2][n][1] * inv0);
            Oh[o1 + c]     = __float2half_rn(acc[rg2][n][2] * inv1);
            Oh[o1 + c + 1] = __float2half_rn(acc[rg2][n][3] * inv1);
        }
    }
}

// ============================================================================
// Out-projection GEMM (1-term fp16) + bias, fp32 out. Warp tile 64x64.
// ============================================================================
__global__ __launch_bounds__(128)
void wgemm1_bias(const h16* __restrict__ Ah, const h16* __restrict__ Bh,
                 const float* __restrict__ bias, float* __restrict__ C,
                 int M, int N, int K)
{
    extern __shared__ h16 dsm[];

    const int tid  = threadIdx.x;
    const int wid  = tid >> 5;
    const int lane = tid & 31;
    const int lr   = lane >> 2;
    const int lc   = (lane & 3) * 2;

    const int mbase = blockIdx.y * 128;
    const int nbase = blockIdx.x * 128;
    const int wm = (wid >> 1) * 64;
    const int wn = (wid & 1) * 64;

    float acc[4][8][4];
    #pragma unroll
    for (int mi = 0; mi < 4; mi++)
        #pragma unroll
        for (int ni = 0; ni < 8; ni++)
            #pragma unroll
            for (int r = 0; r < 4; r++) acc[mi][ni][r] = 0.f;

    const int lrow = tid >> 2;
    const int lch  = tid & 3;
    auto issue_chunk = [&](int k0, int st) {
        h16* base = dsm + st * G_STAGE2;
        #pragma unroll
        for (int rep = 0; rep < 4; rep++) {
            int row = lrow + rep * 32;
            size_t sa = (size_t)(mbase + row) * K + k0 + lch * 8;
            size_t sb = (size_t)(nbase + row) * K + k0 + lch * 8;
            CP16(base + 0 * G_ARR + row * GST + lch * 8, Ah + sa);
            CP16(base + 1 * G_ARR + row * GST + lch * 8, Bh + sb);
        }
        CP_COMMIT();
    };

    const int NCH = K >> 5;
    issue_chunk(0, 0);

    for (int ch = 0; ch < NCH; ++ch) {
        const int cur = ch & 1;
        if (ch + 1 < NCH) { issue_chunk((ch + 1) << 5, cur ^ 1); CP_WAIT1(); }
        else              { CP_WAIT0(); }
        __syncthreads();

        const h16* sA = dsm + cur * G_STAGE2 + 0 * G_ARR;
        const h16* sB = dsm + cur * G_STAGE2 + 1 * G_ARR;

        #pragma unroll
        for (int ks = 0; ks < 32; ks += 16) {
            uint32_t af[4][4];
            #pragma unroll
            for (int mi = 0; mi < 4; mi++) {
                int r0 = wm + mi * 16 + lr;
                af[mi][0] = *(const uint32_t*)(sA + (r0    ) * GST + ks + lc);
                af[mi][1] = *(const uint32_t*)(sA + (r0 + 8) * GST + ks + lc);
                af[mi][2] = *(const uint32_t*)(sA + (r0    ) * GST + ks + 8 + lc);
                af[mi][3] = *(const uint32_t*)(sA + (r0 + 8) * GST + ks + 8 + lc);
            }
            uint32_t bf[8][2];
            #pragma unroll
            for (int ni = 0; ni < 8; ni++) {
                int rn = wn + ni * 8 + lr;
                bf[ni][0] = *(const uint32_t*)(sB + rn * GST + ks + lc);
                bf[ni][1] = *(const uint32_t*)(sB + rn * GST + ks + 8 + lc);
            }
            #pragma unroll
            for (int mi = 0; mi < 4; mi++)
                #pragma unroll
                for (int ni = 0; ni < 8; ni++)
                    mma16816(acc[mi][ni], af[mi], bf[ni]);
        }
        __syncthreads();
    }

    #pragma unroll
    for (int mi = 0; mi < 4; mi++) {
        int row0 = mbase + wm + mi * 16 + lr;
        #pragma unroll
        for (int ni = 0; ni < 8; ni++) {
            int col0 = nbase + wn + ni * 8 + lc;
            float b0 = bias[col0], b1 = bias[col0 + 1];
            float* p0 = C + (size_t)row0 * N + col0;
            float* p1 = C + (size_t)(row0 + 8) * N + col0;
            p0[0] = acc[mi][ni][0] + b0;
            p0[1] = acc[mi][ni][1] + b1;
            p1[0] = acc[mi][ni][2] + b0;
            p1[1] = acc[mi][ni][3] + b1;
        }
    }
}

// ============================================================================
// launch
// ============================================================================
extern "C" void kernel_launch(void* const* d_in, const int* in_sizes, int n_in,
                              void* d_out, int out_size)
{
    const float* x = nullptr; const float* w_qkv = nullptr;
    const float* w_out = nullptr; const float* b_out = nullptr;
    for (int i = 0; i < n_in; i++) {
        long n = in_sizes[i];
        if      (n == (long)MTOT * DD)     x     = (const float*)d_in[i];
        else if (n == 3L * DD * DD)        w_qkv = (const float*)d_in[i];
        else if (n == (long)DD * DD)       w_out = (const float*)d_in[i];
        else if (n == (long)DD)            b_out = (const float*)d_in[i];
    }
    float* out = (float*)d_out;

    float2* trig;
    h16 *xh, *wqh, *aoh, *woh;
    h16 *qhp, *khp, *vth;
    cudaGetSymbolAddress((void**)&trig, g_trig);
    cudaGetSymbolAddress((void**)&xh,  g_x_h);
    cudaGetSymbolAddress((void**)&wqh, g_wq_h);
    cudaGetSymbolAddress((void**)&aoh, g_ao_h);
    cudaGetSymbolAddress((void**)&woh, g_wo_h);
    cudaGetSymbolAddress((void**)&qhp, g_qh);
    cudaGetSymbolAddress((void**)&khp, g_kh);
    cudaGetSymbolAddress((void**)&vth, g_vth);

    cudaFuncSetAttribute(wgemm_qkv_rope,
                         cudaFuncAttributeMaxDynamicSharedMemorySize, G_SMEM2);
    cudaFuncSetAttribute(wgemm1_bias,
                         cudaFuncAttributeMaxDynamicSharedMemorySize, G_SMEM2);
    cudaFuncSetAttribute(attn_mma,
                         cudaFuncAttributeMaxDynamicSharedMemorySize, A_SMEM_BYTES);

    // 0) convert inputs, trig table
    {
        int n1 = MTOT * DD;
        cvt_kernel<<<(n1 + 255) / 256, 256>>>(x, xh, n1);
        int n2 = 3 * DD * DD;
        cvt_kernel<<<(n2 + 255) / 256, 256>>>(w_qkv, wqh, n2);
        trig_kernel<<<(SS * 32 + 255) / 256, 256>>>(trig);
        int n3 = DD * DD;
        cvt_kernel<<<(n3 + 255) / 256, 256>>>(w_out, woh, n3);
    }

    // 1) fused QKV projection + RoPE + layouts (1-term fp16, 64x64 warp tile)
    wgemm_qkv_rope<<<dim3((3 * DD) / 128, MTOT / 128), 128, G_SMEM2>>>(
        xh, wqh, trig, qhp, khp, vth);

    // 2) attention (fixed-offset softmax, 32 q-rows/warp)
    attn_mma<<<dim3(SS / 128, BB * HH), 128, A_SMEM_BYTES>>>(
        qhp, khp, vth, aoh);

    // 3) output projection (1-term) + bias (64x64 warp tile)
    wgemm1_bias<<<dim3(DD / 128, MTOT / 128), 128, G_SMEM2>>>(
        aoh, woh, b_out, out, MTOT, DD, DD);
}